// round 1
// baseline (speedup 1.0000x reference)
#include <cuda_runtime.h>
#include <cstdint>

#define N_NODES 100000
#define M_HE    200000
#define NE      2000000
#define IN_F    16
#define HID     64
#define NT      2

// ---------------- scratch (no allocations allowed) ----------------
__device__ __align__(16) float g_xw[(size_t)N_NODES * 128];    // [n][t*64+c]
__device__ __align__(16) float g_efeat[(size_t)M_HE * 128];    // [he][t*64+c]
__device__ __align__(16) float g_acc[(size_t)N_NODES * 128];   // [n][t*64+c]
__device__ __align__(16) float g_Bdeg[NT * M_HE];
__device__ __align__(16) float g_Ddeg[NT * N_NODES];
__device__ __align__(16) float g_h[(size_t)N_NODES * HID];

// ---------------- zero scratch that is accumulated into ----------------
__global__ void k_zero() {
    const size_t EF4 = (size_t)M_HE * 32;      // e_feat in float4
    const size_t AC4 = (size_t)N_NODES * 32;   // acc in float4
    const size_t BD4 = (NT * M_HE) / 4;
    const size_t DD4 = (NT * N_NODES) / 4;
    float4 z = make_float4(0.f, 0.f, 0.f, 0.f);
    size_t stride = (size_t)gridDim.x * blockDim.x;
    size_t i0 = (size_t)blockIdx.x * blockDim.x + threadIdx.x;
    for (size_t k = i0; k < EF4; k += stride) ((float4*)g_efeat)[k] = z;
    for (size_t k = i0; k < AC4; k += stride) ((float4*)g_acc)[k] = z;
    for (size_t k = i0; k < BD4; k += stride) ((float4*)g_Bdeg)[k] = z;
    for (size_t k = i0; k < DD4; k += stride) ((float4*)g_Ddeg)[k] = z;
}

// ---------------- xw = x @ W_conv[t]  for both t ----------------
// block: 128 threads, 8 nodes/block. thread = output column c in [0,128)
__global__ void k_xw(const float* __restrict__ x, const float* __restrict__ Wc) {
    __shared__ float Ws[NT * IN_F * HID];   // 2048
    __shared__ float xs[8 * IN_F];          // 128
    int tid = threadIdx.x;
    int n0 = blockIdx.x * 8;
    #pragma unroll
    for (int i = tid; i < NT * IN_F * HID; i += 128) Ws[i] = Wc[i];
    xs[tid] = x[(size_t)n0 * IN_F + tid];
    __syncthreads();
    int c = tid;
    int t = c >> 6, cc = c & 63;
    const float* w = &Ws[t * (IN_F * HID) + cc];
    #pragma unroll
    for (int nd = 0; nd < 8; nd++) {
        float a = 0.f;
        #pragma unroll
        for (int k = 0; k < IN_F; k++) a += xs[nd * IN_F + k] * w[k * HID];
        g_xw[(size_t)(n0 + nd) * 128 + c] = a;
    }
}

// ---------------- degree counting ----------------
__global__ void k_deg(const int* __restrict__ en, const int* __restrict__ eh,
                      const int* __restrict__ ea) {
    int i = blockIdx.x * blockDim.x + threadIdx.x;
    if (i >= NE) return;
    int t = ea[i];
    atomicAdd(&g_Bdeg[t * M_HE + eh[i]], 1.f);
    atomicAdd(&g_Ddeg[t * N_NODES + en[i]], 1.f);
}

__device__ __forceinline__ void red_v4(float* dst, float4 v) {
    asm volatile("red.global.add.v4.f32 [%0], {%1,%2,%3,%4};"
                 :: "l"(dst), "f"(v.x), "f"(v.y), "f"(v.z), "f"(v.w)
                 : "memory");
}

// ---------------- scatter 1: node -> hyperedge ----------------
// 16 threads per incidence, one float4 each (64 floats of matching type)
__global__ void k_scat1(const int* __restrict__ en, const int* __restrict__ eh,
                        const int* __restrict__ ea) {
    int idx = blockIdx.x * blockDim.x + threadIdx.x;
    int i = idx >> 4, q = idx & 15;
    if (i >= NE) return;
    int t = __ldg(&ea[i]);
    int n = __ldg(&en[i]);
    int he = __ldg(&eh[i]);
    const float4 v = ((const float4*)g_xw)[(size_t)n * 32 + t * 16 + q];
    float* dst = &g_efeat[((size_t)he * 32 + t * 16 + q) * 4];
    red_v4(dst, v);
}

// ---------------- scatter 2: hyperedge -> node (with B^-1) ----------------
__global__ void k_scat2(const int* __restrict__ en, const int* __restrict__ eh,
                        const int* __restrict__ ea) {
    int idx = blockIdx.x * blockDim.x + threadIdx.x;
    int i = idx >> 4, q = idx & 15;
    if (i >= NE) return;
    int t = __ldg(&ea[i]);
    int n = __ldg(&en[i]);
    int he = __ldg(&eh[i]);
    float binv = 1.0f / __ldg(&g_Bdeg[t * M_HE + he]);   // >=1 for touched (he,t)
    float4 v = ((const float4*)g_efeat)[(size_t)he * 32 + t * 16 + q];
    v.x *= binv; v.y *= binv; v.z *= binv; v.w *= binv;
    float* dst = &g_acc[((size_t)n * 32 + t * 16 + q) * 4];
    red_v4(dst, v);
}

// ---------------- mix: u = acc*Dinv + b_conv ; h = relu(u @ W_mix + b_mix) ----------------
// block: 256 threads, 64 nodes. 4 nodes x 4 cols register tile per thread.
__global__ void k_mix(const float* __restrict__ Wmix, const float* __restrict__ bmix,
                      const float* __restrict__ bconv) {
    extern __shared__ float sm[];
    float* u_s  = sm;                 // 64 * 130
    float* Wm_s = sm + 64 * 130;      // 128 * 64
    float* bm_s = Wm_s + 128 * 64;    // 64
    float* bc_s = bm_s + 64;          // 128
    int tid = threadIdx.x;
    int n0 = blockIdx.x * 64;

    for (int i = tid; i < 128 * 64; i += 256) Wm_s[i] = Wmix[i];
    if (tid < 64)  bm_s[tid] = bmix[tid];
    if (tid < 128) bc_s[tid] = bconv[tid];
    __syncthreads();

    // build u tile
    for (int idx = tid; idx < 64 * 128; idx += 256) {
        int nd = idx >> 7, c = idx & 127;
        int n = n0 + nd;
        float u = 0.f;
        if (n < N_NODES) {
            int t = c >> 6;
            float dd = g_Ddeg[t * N_NODES + n];
            float dinv = (dd > 0.f) ? (1.f / dd) : 0.f;
            u = g_acc[(size_t)n * 128 + c] * dinv + bc_s[c];
        }
        u_s[nd * 130 + c] = u;
    }
    __syncthreads();

    int colg = tid & 15;     // 4 cols each
    int nodeg = tid >> 4;    // 4 nodes each
    float acc[4][4];
    #pragma unroll
    for (int i = 0; i < 4; i++)
        #pragma unroll
        for (int j = 0; j < 4; j++) acc[i][j] = 0.f;

    for (int k = 0; k < 128; k++) {
        float w0 = Wm_s[k * 64 + colg * 4 + 0];
        float w1 = Wm_s[k * 64 + colg * 4 + 1];
        float w2 = Wm_s[k * 64 + colg * 4 + 2];
        float w3 = Wm_s[k * 64 + colg * 4 + 3];
        #pragma unroll
        for (int i = 0; i < 4; i++) {
            float uv = u_s[(nodeg * 4 + i) * 130 + k];
            acc[i][0] += uv * w0;
            acc[i][1] += uv * w1;
            acc[i][2] += uv * w2;
            acc[i][3] += uv * w3;
        }
    }

    #pragma unroll
    for (int i = 0; i < 4; i++) {
        int n = n0 + nodeg * 4 + i;
        if (n < N_NODES) {
            #pragma unroll
            for (int j = 0; j < 4; j++) {
                int col = colg * 4 + j;
                float h = acc[i][j] + bm_s[col];
                g_h[(size_t)n * 64 + col] = fmaxf(h, 0.f);
            }
        }
    }
}

__device__ __forceinline__ float sigf(float x) { return 1.f / (1.f + expf(-x)); }

// ---------------- GRU + output projection ----------------
// block: 256 threads, 32 nodes. Each thread: 4 nodes x 2 gate-cols, 6 dot64s.
__global__ void k_gru(const float* __restrict__ hprev,
                      const float* __restrict__ Wih, const float* __restrict__ Whh,
                      const float* __restrict__ bih, const float* __restrict__ bhh,
                      const float* __restrict__ Wout, const float* __restrict__ bout,
                      float* __restrict__ out_h, float* __restrict__ out_p) {
    extern __shared__ float sm[];
    float* Wih_s = sm;                    // 192*65 = 12480
    float* Whh_s = Wih_s + 192 * 65;      // 12480
    float* h_s   = Whh_s + 192 * 65;      // 32*65 = 2080
    float* hp_s  = h_s  + 32 * 65;        // 2080
    float* hn_s  = hp_s + 32 * 65;        // 2080
    float* bih_s = hn_s + 32 * 65;        // 192
    float* bhh_s = bih_s + 192;           // 192
    float* wo_s  = bhh_s + 192;           // 192 (64 x 3)
    float* bo_s  = wo_s + 192;            // 4

    int tid = threadIdx.x;
    int n0 = blockIdx.x * 32;

    for (int i = tid; i < 192 * 64; i += 256) {
        int row = i >> 6, k = i & 63;
        Wih_s[row * 65 + k] = Wih[i];
        Whh_s[row * 65 + k] = Whh[i];
    }
    for (int i = tid; i < 32 * 64; i += 256) {
        int nd = i >> 6, c = i & 63;
        h_s[nd * 65 + c]  = g_h[(size_t)(n0 + nd) * 64 + c];
        hp_s[nd * 65 + c] = hprev[(size_t)(n0 + nd) * 64 + c];
    }
    if (tid < 192) {
        bih_s[tid] = bih[tid];
        bhh_s[tid] = bhh[tid];
        int j = tid / 3, k = tid % 3;
        wo_s[tid] = Wout[j * 64 + k];
    }
    if (tid < 3) bo_s[tid] = bout[tid];
    __syncthreads();

    int jg = tid & 31;      // 2 gate-cols each
    int nodeg = tid >> 5;   // 4 nodes each
    float a_ir[4][2], a_iz[4][2], a_in[4][2], a_hr[4][2], a_hz[4][2], a_hn[4][2];
    #pragma unroll
    for (int i = 0; i < 4; i++)
        #pragma unroll
        for (int j = 0; j < 2; j++) {
            a_ir[i][j] = a_iz[i][j] = a_in[i][j] = 0.f;
            a_hr[i][j] = a_hz[i][j] = a_hn[i][j] = 0.f;
        }

    for (int k = 0; k < 64; k++) {
        float hv[4], pv[4];
        #pragma unroll
        for (int i = 0; i < 4; i++) {
            hv[i] = h_s[(nodeg * 4 + i) * 65 + k];
            pv[i] = hp_s[(nodeg * 4 + i) * 65 + k];
        }
        #pragma unroll
        for (int jj = 0; jj < 2; jj++) {
            int row = jg * 2 + jj;
            float wir = Wih_s[row * 65 + k];
            float wiz = Wih_s[(64 + row) * 65 + k];
            float win = Wih_s[(128 + row) * 65 + k];
            float whr = Whh_s[row * 65 + k];
            float whz = Whh_s[(64 + row) * 65 + k];
            float whn = Whh_s[(128 + row) * 65 + k];
            #pragma unroll
            for (int i = 0; i < 4; i++) {
                a_ir[i][jj] += hv[i] * wir;
                a_iz[i][jj] += hv[i] * wiz;
                a_in[i][jj] += hv[i] * win;
                a_hr[i][jj] += pv[i] * whr;
                a_hz[i][jj] += pv[i] * whz;
                a_hn[i][jj] += pv[i] * whn;
            }
        }
    }

    #pragma unroll
    for (int jj = 0; jj < 2; jj++) {
        int row = jg * 2 + jj;
        float br_i = bih_s[row],        br_h = bhh_s[row];
        float bz_i = bih_s[64 + row],   bz_h = bhh_s[64 + row];
        float bn_i = bih_s[128 + row],  bn_h = bhh_s[128 + row];
        #pragma unroll
        for (int i = 0; i < 4; i++) {
            int nd = nodeg * 4 + i;
            float r = sigf(a_ir[i][jj] + br_i + a_hr[i][jj] + br_h);
            float z = sigf(a_iz[i][jj] + bz_i + a_hz[i][jj] + bz_h);
            float nn = tanhf(a_in[i][jj] + bn_i + r * (a_hn[i][jj] + bn_h));
            float hp = hp_s[nd * 65 + row];
            float hx = (1.f - z) * nn + z * hp;
            out_h[(size_t)(n0 + nd) * 64 + row] = hx;
            hn_s[nd * 65 + row] = hx;
        }
    }
    __syncthreads();

    // pred_xyz = h_next @ W_out[:, :3] + b_out[:3]
    if (tid < 96) {
        int nd = tid / 3, k = tid % 3;
        float a = bo_s[k];
        #pragma unroll
        for (int j = 0; j < 64; j++) a += hn_s[nd * 65 + j] * wo_s[j * 3 + k];
        out_p[(size_t)(n0 + nd) * 3 + k] = a;
    }
}

extern "C" void kernel_launch(void* const* d_in, const int* in_sizes, int n_in,
                              void* d_out, int out_size) {
    const float* x       = (const float*)d_in[0];
    const float* h_prev  = (const float*)d_in[1];
    const int* en        = (const int*)d_in[2];
    const int* eh        = (const int*)d_in[3];
    const int* ea        = (const int*)d_in[4];
    const float* W_conv  = (const float*)d_in[5];
    const float* b_conv  = (const float*)d_in[6];
    const float* W_mix   = (const float*)d_in[7];
    const float* b_mix   = (const float*)d_in[8];
    const float* W_ih    = (const float*)d_in[9];
    const float* W_hh    = (const float*)d_in[10];
    const float* b_ih    = (const float*)d_in[11];
    const float* b_hh    = (const float*)d_in[12];
    const float* W_out   = (const float*)d_in[13];
    const float* b_out   = (const float*)d_in[14];
    float* out = (float*)d_out;
    float* out_h = out;                       // [N, 64]
    float* out_p = out + (size_t)N_NODES * 64;  // [N, 3]

    static const int mix_smem = (64 * 130 + 128 * 64 + 64 + 128) * 4;
    static const int gru_smem = (192 * 65 * 2 + 32 * 65 * 3 + 192 * 3 + 4) * 4;
    cudaFuncSetAttribute(k_mix, cudaFuncAttributeMaxDynamicSharedMemorySize, mix_smem);
    cudaFuncSetAttribute(k_gru, cudaFuncAttributeMaxDynamicSharedMemorySize, gru_smem);

    k_zero<<<4736, 256>>>();
    k_xw<<<N_NODES / 8, 128>>>(x, W_conv);
    k_deg<<<(NE + 255) / 256, 256>>>(en, eh, ea);
    k_scat1<<<(NE * 16) / 256, 256>>>(en, eh, ea);
    k_scat2<<<(NE * 16) / 256, 256>>>(en, eh, ea);
    k_mix<<<(N_NODES + 63) / 64, 256, mix_smem>>>(W_mix, b_mix, b_conv);
    k_gru<<<N_NODES / 32, 256, gru_smem>>>(h_prev, W_ih, W_hh, b_ih, b_hh,
                                           W_out, b_out, out_h, out_p);
}

// round 3
// speedup vs baseline: 1.0825x; 1.0825x over previous
#include <cuda_runtime.h>
#include <cstdint>

#define N_NODES 100000
#define M_HE    200000
#define NE      2000000
#define IN_F    16
#define HID     64
#define NT      2

// ---------------- scratch (no allocations allowed) ----------------
__device__ __align__(16) float g_xw[(size_t)N_NODES * 128];    // [n][t*64+c]
__device__ __align__(16) float g_efeat[(size_t)M_HE * 128];    // [he][t*64+c]
__device__ __align__(16) float g_acc[(size_t)N_NODES * 128];   // [n][t*64+c]
__device__ __align__(16) float g_Bdeg[NT * M_HE];
__device__ __align__(16) float g_Ddeg[NT * N_NODES];
__device__ __align__(16) float g_h[(size_t)N_NODES * HID];
__device__ __align__(16) int2  g_pairs[NT][NE];                // compacted (n, he)
__device__ int g_cnt[NT];

// ---------------- small zero: degrees + counters ----------------
__global__ void k_zero_small() {
    int i = blockIdx.x * blockDim.x + threadIdx.x;
    if (i < NT * M_HE)    g_Bdeg[i] = 0.f;
    if (i < NT * N_NODES) g_Ddeg[i] = 0.f;
    if (i < NT)           g_cnt[i] = 0;
}

// ---------------- zero one type-half of g_efeat / g_acc (device symbols!) ----------------
__global__ void k_zero_efeat_t(int t) {
    int idx = blockIdx.x * blockDim.x + threadIdx.x;
    int r = idx >> 4, q = idx & 15;
    if (r >= M_HE) return;
    ((float4*)g_efeat)[(size_t)r * 32 + t * 16 + q] = make_float4(0.f, 0.f, 0.f, 0.f);
}
__global__ void k_zero_acc_t(int t) {
    int idx = blockIdx.x * blockDim.x + threadIdx.x;
    int r = idx >> 4, q = idx & 15;
    if (r >= N_NODES) return;
    ((float4*)g_acc)[(size_t)r * 32 + t * 16 + q] = make_float4(0.f, 0.f, 0.f, 0.f);
}

// ---------------- xw = x @ W_conv[t] for both t ----------------
__global__ void k_xw(const float* __restrict__ x, const float* __restrict__ Wc) {
    __shared__ float Ws[NT * IN_F * HID];
    __shared__ float xs[8 * IN_F];
    int tid = threadIdx.x;
    int n0 = blockIdx.x * 8;
    #pragma unroll
    for (int i = tid; i < NT * IN_F * HID; i += 128) Ws[i] = Wc[i];
    xs[tid] = x[(size_t)n0 * IN_F + tid];
    __syncthreads();
    int c = tid;
    int t = c >> 6, cc = c & 63;
    const float* w = &Ws[t * (IN_F * HID) + cc];
    #pragma unroll
    for (int nd = 0; nd < 8; nd++) {
        float a = 0.f;
        #pragma unroll
        for (int k = 0; k < IN_F; k++) a += xs[nd * IN_F + k] * w[k * HID];
        g_xw[(size_t)(n0 + nd) * 128 + c] = a;
    }
}

// ---------------- degree counting + warp-aggregated per-type compaction ----------------
__global__ void k_degcompact(const int* __restrict__ en, const int* __restrict__ eh,
                             const int* __restrict__ ea) {
    int i = blockIdx.x * 128 + threadIdx.x;
    int t = ea[i], n = en[i], he = eh[i];
    atomicAdd(&g_Bdeg[t * M_HE + he], 1.f);
    atomicAdd(&g_Ddeg[t * N_NODES + n], 1.f);
    unsigned b1 = __ballot_sync(0xffffffffu, t == 1);
    unsigned grp = t ? b1 : ~b1;
    int lane = threadIdx.x & 31;
    int rank = __popc(grp & ((1u << lane) - 1u));
    int leader = __ffs(grp) - 1;
    int base = 0;
    if (lane == leader) base = atomicAdd(&g_cnt[t], __popc(grp));
    base = __shfl_sync(0xffffffffu, base, leader);
    g_pairs[t][base + rank] = make_int2(n, he);
}

__device__ __forceinline__ void red_v4(float* dst, float4 v) {
    asm volatile("red.global.add.v4.f32 [%0], {%1,%2,%3,%4};"
                 :: "l"(dst), "f"(v.x), "f"(v.y), "f"(v.z), "f"(v.w)
                 : "memory");
}

// ---------------- scatter 1 (per type): node -> hyperedge ----------------
__global__ void k_scat1_t(int t) {
    int idx = blockIdx.x * blockDim.x + threadIdx.x;
    int i = idx >> 4, q = idx & 15;
    if (i >= g_cnt[t]) return;
    int2 p = g_pairs[t][i];                    // (n, he)
    float4 v = ((const float4*)g_xw)[(size_t)p.x * 32 + t * 16 + q];
    red_v4(&g_efeat[((size_t)p.y * 32 + t * 16 + q) * 4], v);
}

// ---------------- scatter 2 (per type): hyperedge -> node, with B^-1 ----------------
__global__ void k_scat2_t(int t) {
    int idx = blockIdx.x * blockDim.x + threadIdx.x;
    int i = idx >> 4, q = idx & 15;
    if (i >= g_cnt[t]) return;
    int2 p = g_pairs[t][i];
    float binv = 1.0f / __ldg(&g_Bdeg[t * M_HE + p.y]);
    float4 v = ((const float4*)g_efeat)[(size_t)p.y * 32 + t * 16 + q];
    v.x *= binv; v.y *= binv; v.z *= binv; v.w *= binv;
    red_v4(&g_acc[((size_t)p.x * 32 + t * 16 + q) * 4], v);
}

// ---------------- mix: u = acc*Dinv + b_conv ; h = relu(u @ W_mix + b_mix) ----------------
__global__ void k_mix(const float* __restrict__ Wmix, const float* __restrict__ bmix,
                      const float* __restrict__ bconv) {
    extern __shared__ float sm[];
    float* u_s  = sm;                 // 64 * 130
    float* Wm_s = sm + 64 * 130;      // 128 * 64
    float* bm_s = Wm_s + 128 * 64;    // 64
    float* bc_s = bm_s + 64;          // 128
    int tid = threadIdx.x;
    int n0 = blockIdx.x * 64;

    for (int i = tid; i < 128 * 64; i += 256) Wm_s[i] = Wmix[i];
    if (tid < 64)  bm_s[tid] = bmix[tid];
    if (tid < 128) bc_s[tid] = bconv[tid];
    __syncthreads();

    for (int idx = tid; idx < 64 * 128; idx += 256) {
        int nd = idx >> 7, c = idx & 127;
        int n = n0 + nd;
        float u = 0.f;
        if (n < N_NODES) {
            int t = c >> 6;
            float dd = g_Ddeg[t * N_NODES + n];
            float dinv = (dd > 0.f) ? (1.f / dd) : 0.f;
            u = g_acc[(size_t)n * 128 + c] * dinv + bc_s[c];
        }
        u_s[nd * 130 + c] = u;
    }
    __syncthreads();

    int colg = tid & 15;
    int nodeg = tid >> 4;
    float acc[4][4];
    #pragma unroll
    for (int i = 0; i < 4; i++)
        #pragma unroll
        for (int j = 0; j < 4; j++) acc[i][j] = 0.f;

    for (int k = 0; k < 128; k++) {
        float w0 = Wm_s[k * 64 + colg * 4 + 0];
        float w1 = Wm_s[k * 64 + colg * 4 + 1];
        float w2 = Wm_s[k * 64 + colg * 4 + 2];
        float w3 = Wm_s[k * 64 + colg * 4 + 3];
        #pragma unroll
        for (int i = 0; i < 4; i++) {
            float uv = u_s[(nodeg * 4 + i) * 130 + k];
            acc[i][0] += uv * w0;
            acc[i][1] += uv * w1;
            acc[i][2] += uv * w2;
            acc[i][3] += uv * w3;
        }
    }

    #pragma unroll
    for (int i = 0; i < 4; i++) {
        int n = n0 + nodeg * 4 + i;
        if (n < N_NODES) {
            #pragma unroll
            for (int j = 0; j < 4; j++) {
                int col = colg * 4 + j;
                float h = acc[i][j] + bm_s[col];
                g_h[(size_t)n * 64 + col] = fmaxf(h, 0.f);
            }
        }
    }
}

__device__ __forceinline__ float sigf(float x) { return 1.f / (1.f + expf(-x)); }

#define FMA2(d, a, b) asm("fma.rn.f32x2 %0, %1, %2, %0;" : "+l"(d) : "l"(a), "l"(b))

__device__ __forceinline__ float hsum2(uint64_t v) {
    float lo, hi;
    asm("mov.b64 {%0,%1}, %2;" : "=f"(lo), "=f"(hi) : "l"(v));
    return lo + hi;
}

// W interleaved index: 4 consecutive k per row chunk -> conflict-free LDS.128
__device__ __forceinline__ int widx(int row, int k) {
    return (k >> 2) * 768 + row * 4 + (k & 3);
}

// ---------------- GRU + output projection (persistent, f32x2 over k-pairs) ----------------
__global__ __launch_bounds__(256, 1)
void k_gru(const float* __restrict__ hprev,
           const float* __restrict__ Wih, const float* __restrict__ Whh,
           const float* __restrict__ bih, const float* __restrict__ bhh,
           const float* __restrict__ Wout, const float* __restrict__ bout,
           float* __restrict__ out_h, float* __restrict__ out_p) {
    extern __shared__ float sm[];
    float* Wih_s = sm;                    // 12288 (interleaved)
    float* Whh_s = Wih_s + 12288;         // 12288
    float* h_s   = Whh_s + 12288;         // 32*68
    float* hp_s  = h_s  + 32 * 68;        // 32*68
    float* hn_s  = hp_s + 32 * 68;        // 32*68
    float* bih_s = hn_s + 32 * 68;        // 192
    float* bhh_s = bih_s + 192;           // 192
    float* wo_s  = bhh_s + 192;           // 192
    float* bo_s  = wo_s + 192;            // 4

    int tid = threadIdx.x;
    for (int i = tid; i < 192 * 64; i += 256) {
        int row = i >> 6, k = i & 63;
        Wih_s[widx(row, k)] = Wih[i];
        Whh_s[widx(row, k)] = Whh[i];
    }
    if (tid < 192) {
        bih_s[tid] = bih[tid];
        bhh_s[tid] = bhh[tid];
        int j = tid / 3, k = tid % 3;
        wo_s[tid] = Wout[j * 64 + k];
    }
    if (tid < 3) bo_s[tid] = bout[tid];
    __syncthreads();

    const int lane = tid & 31;
    const int wp = tid >> 5;
    const int nbase = wp * 4;
    const int c0 = lane, c1 = lane + 32;

    for (int tile = blockIdx.x; tile < N_NODES / 32; tile += gridDim.x) {
        int n0 = tile * 32;
        for (int i = tid; i < 32 * 64; i += 256) {
            int nd = i >> 6, k = i & 63;
            h_s[nd * 68 + k]  = g_h[(size_t)(n0 + nd) * 64 + k];
            hp_s[nd * 68 + k] = hprev[(size_t)(n0 + nd) * 64 + k];
        }
        __syncthreads();

        uint64_t ai[3][4][2], ah[3][4][2];
        #pragma unroll
        for (int g = 0; g < 3; g++)
            #pragma unroll
            for (int nd = 0; nd < 4; nd++)
                #pragma unroll
                for (int c = 0; c < 2; c++) { ai[g][nd][c] = 0ull; ah[g][nd][c] = 0ull; }

        #pragma unroll 2
        for (int k4 = 0; k4 < 16; k4++) {
            int wb = k4 * 768;
            ulonglong2 wi[2][3], wh[2][3];
            #pragma unroll
            for (int g = 0; g < 3; g++) {
                wi[0][g] = *(const ulonglong2*)&Wih_s[wb + (g * 64 + c0) * 4];
                wi[1][g] = *(const ulonglong2*)&Wih_s[wb + (g * 64 + c1) * 4];
                wh[0][g] = *(const ulonglong2*)&Whh_s[wb + (g * 64 + c0) * 4];
                wh[1][g] = *(const ulonglong2*)&Whh_s[wb + (g * 64 + c1) * 4];
            }
            #pragma unroll
            for (int nd = 0; nd < 4; nd++) {
                ulonglong2 hv = *(const ulonglong2*)&h_s[(nbase + nd) * 68 + k4 * 4];
                ulonglong2 pv = *(const ulonglong2*)&hp_s[(nbase + nd) * 68 + k4 * 4];
                #pragma unroll
                for (int c = 0; c < 2; c++) {
                    #pragma unroll
                    for (int g = 0; g < 3; g++) {
                        FMA2(ai[g][nd][c], hv.x, wi[c][g].x);
                        FMA2(ai[g][nd][c], hv.y, wi[c][g].y);
                        FMA2(ah[g][nd][c], pv.x, wh[c][g].x);
                        FMA2(ah[g][nd][c], pv.y, wh[c][g].y);
                    }
                }
            }
        }

        #pragma unroll
        for (int nd = 0; nd < 4; nd++) {
            #pragma unroll
            for (int c = 0; c < 2; c++) {
                int col = c ? c1 : c0;
                int n = n0 + nbase + nd;
                float ir = hsum2(ai[0][nd][c]) + bih_s[col];
                float iz = hsum2(ai[1][nd][c]) + bih_s[64 + col];
                float in_ = hsum2(ai[2][nd][c]) + bih_s[128 + col];
                float hr = hsum2(ah[0][nd][c]) + bhh_s[col];
                float hz = hsum2(ah[1][nd][c]) + bhh_s[64 + col];
                float hn = hsum2(ah[2][nd][c]) + bhh_s[128 + col];
                float r = sigf(ir + hr);
                float z = sigf(iz + hz);
                float nn = tanhf(in_ + r * hn);
                float hp = hp_s[(nbase + nd) * 68 + col];
                float hx = (1.f - z) * nn + z * hp;
                out_h[(size_t)n * 64 + col] = hx;
                hn_s[(nbase + nd) * 68 + col] = hx;
            }
        }
        __syncthreads();

        if (tid < 96) {
            int nd = tid / 3, k = tid % 3;
            float a = bo_s[k];
            #pragma unroll
            for (int j = 0; j < 64; j++) a += hn_s[nd * 68 + j] * wo_s[j * 3 + k];
            out_p[(size_t)(n0 + nd) * 3 + k] = a;
        }
        __syncthreads();
    }
}

extern "C" void kernel_launch(void* const* d_in, const int* in_sizes, int n_in,
                              void* d_out, int out_size) {
    const float* x       = (const float*)d_in[0];
    const float* h_prev  = (const float*)d_in[1];
    const int* en        = (const int*)d_in[2];
    const int* eh        = (const int*)d_in[3];
    const int* ea        = (const int*)d_in[4];
    const float* W_conv  = (const float*)d_in[5];
    const float* b_conv  = (const float*)d_in[6];
    const float* W_mix   = (const float*)d_in[7];
    const float* b_mix   = (const float*)d_in[8];
    const float* W_ih    = (const float*)d_in[9];
    const float* W_hh    = (const float*)d_in[10];
    const float* b_ih    = (const float*)d_in[11];
    const float* b_hh    = (const float*)d_in[12];
    const float* W_out   = (const float*)d_in[13];
    const float* b_out   = (const float*)d_in[14];
    float* out = (float*)d_out;
    float* out_h = out;
    float* out_p = out + (size_t)N_NODES * 64;

    static const int mix_smem = (64 * 130 + 128 * 64 + 64 + 128) * 4;
    static const int gru_smem = (12288 * 2 + 32 * 68 * 3 + 192 * 3 + 4) * 4;
    cudaFuncSetAttribute(k_mix, cudaFuncAttributeMaxDynamicSharedMemorySize, mix_smem);
    cudaFuncSetAttribute(k_gru, cudaFuncAttributeMaxDynamicSharedMemorySize, gru_smem);

    k_zero_small<<<(NT * M_HE + 255) / 256, 256>>>();
    k_xw<<<N_NODES / 8, 128>>>(x, W_conv);
    k_degcompact<<<NE / 128, 128>>>(en, eh, ea);

    const int scat_blocks = (NE * 16) / 256;   // worst-case; early-exit on g_cnt
    for (int t = 0; t < NT; t++) {
        k_zero_efeat_t<<<(M_HE * 16) / 256, 256>>>(t);
        k_scat1_t<<<scat_blocks, 256>>>(t);
        k_zero_acc_t<<<(N_NODES * 16 + 255) / 256, 256>>>(t);
        k_scat2_t<<<scat_blocks, 256>>>(t);
    }

    k_mix<<<(N_NODES + 63) / 64, 256, mix_smem>>>(W_mix, b_mix, b_conv);
    k_gru<<<152, 256, gru_smem>>>(h_prev, W_ih, W_hh, b_ih, b_hh,
                                  W_out, b_out, out_h, out_p);
}

// round 4
// speedup vs baseline: 1.7677x; 1.6331x over previous
#include <cuda_runtime.h>
#include <cstdint>

#define N_NODES 100000
#define M_HE    200000
#define NE      2000000
#define IN_F    16
#define HID     64
#define NT      2

#define SB (NT * M_HE)     // 400000 hyperedge-type rows
#define SD (NT * N_NODES)  // 200000 node-type rows
#define NBB ((SB + 1023) / 1024)   // 391
#define NBD ((SD + 1023) / 1024)   // 196

// ---------------- scratch (no allocations allowed) ----------------
__device__ __align__(16) float g_xw[(size_t)N_NODES * 128];    // [n][t*64+c]
__device__ __align__(16) float g_efeat[(size_t)M_HE * 128];    // [he][t*64+c]
__device__ __align__(16) float g_acc[(size_t)N_NODES * 128];   // [n][t*64+c] (u pre-bias)
__device__ __align__(16) float g_h[(size_t)N_NODES * HID];
__device__ int g_hB[SB], g_hD[SD];        // histograms (counts)
__device__ int g_offB[SB], g_offD[SD];    // CSR row starts (exclusive scan)
__device__ int g_curB[SB], g_curD[SD];    // placement cursors
__device__ int g_bsum[1024];              // block sums: [0..511]=B, [512..1023]=D
__device__ int g_idxB[NE];                // he-sorted: node ids
__device__ int g_idxD[NE];                // node-sorted: hyperedge ids

// ---------------- zero histograms ----------------
__global__ void k_zero_hist() {
    int i = blockIdx.x * blockDim.x + threadIdx.x;
    if (i < SB) g_hB[i] = 0;
    if (i < SD) g_hD[i] = 0;
}

// ---------------- histogram ----------------
__global__ void k_hist(const int* __restrict__ en, const int* __restrict__ eh,
                       const int* __restrict__ ea) {
    int i = blockIdx.x * blockDim.x + threadIdx.x;
    if (i >= NE) return;
    int t = ea[i];
    atomicAdd(&g_hB[t * M_HE + eh[i]], 1);
    atomicAdd(&g_hD[t * N_NODES + en[i]], 1);
}

// ---------------- scan step 1: per-block (1024 elems) exclusive scan ----------------
__global__ void k_scan_local(int which) {
    const int n   = which ? SD : SB;
    const int* in = which ? g_hD : g_hB;
    int* out      = which ? g_offD : g_offB;
    int* sums     = g_bsum + which * 512;
    int tid = threadIdx.x;
    int base = blockIdx.x * 1024 + tid * 4;
    int v0 = (base + 0 < n) ? in[base + 0] : 0;
    int v1 = (base + 1 < n) ? in[base + 1] : 0;
    int v2 = (base + 2 < n) ? in[base + 2] : 0;
    int v3 = (base + 3 < n) ? in[base + 3] : 0;
    int s = v0 + v1 + v2 + v3;
    __shared__ int sh[256];
    sh[tid] = s;
    __syncthreads();
    for (int d = 1; d < 256; d <<= 1) {
        int v = (tid >= d) ? sh[tid - d] : 0;
        __syncthreads();
        sh[tid] += v;
        __syncthreads();
    }
    int excl = sh[tid] - s;
    if (base + 0 < n) out[base + 0] = excl;
    if (base + 1 < n) out[base + 1] = excl + v0;
    if (base + 2 < n) out[base + 2] = excl + v0 + v1;
    if (base + 3 < n) out[base + 3] = excl + v0 + v1 + v2;
    if (tid == 255) sums[blockIdx.x] = excl + s;
}

// ---------------- scan step 2: exclusive scan of block sums (single block) ----------------
__global__ void k_scan_tops(int which) {
    const int nb = which ? NBD : NBB;
    int* sums = g_bsum + which * 512;
    int tid = threadIdx.x;  // 512 threads
    __shared__ int sh[512];
    int s = (tid < nb) ? sums[tid] : 0;
    sh[tid] = s;
    __syncthreads();
    for (int d = 1; d < 512; d <<= 1) {
        int v = (tid >= d) ? sh[tid - d] : 0;
        __syncthreads();
        sh[tid] += v;
        __syncthreads();
    }
    if (tid < nb) sums[tid] = sh[tid] - s;
}

// ---------------- scan step 3: add block offsets; init cursors ----------------
__global__ void k_scan_add(int which) {
    const int n = which ? SD : SB;
    int* out    = which ? g_offD : g_offB;
    int* cur    = which ? g_curD : g_curB;
    const int* sums = g_bsum + which * 512;
    int i = blockIdx.x * blockDim.x + threadIdx.x;
    if (i >= n) return;
    int v = out[i] + sums[i >> 10];
    out[i] = v;
    cur[i] = v;
}

// ---------------- placement: counting-sort scatter of incidences ----------------
__global__ void k_place(const int* __restrict__ en, const int* __restrict__ eh,
                        const int* __restrict__ ea) {
    int i = blockIdx.x * blockDim.x + threadIdx.x;
    if (i >= NE) return;
    int t = ea[i], n = en[i], he = eh[i];
    int pb = atomicAdd(&g_curB[t * M_HE + he], 1);
    g_idxB[pb] = n;
    int pd = atomicAdd(&g_curD[t * N_NODES + n], 1);
    g_idxD[pd] = he;
}

// ---------------- xw = x @ W_conv[t] for both t ----------------
__global__ void k_xw(const float* __restrict__ x, const float* __restrict__ Wc) {
    __shared__ float Ws[NT * IN_F * HID];
    __shared__ float xs[8 * IN_F];
    int tid = threadIdx.x;
    int n0 = blockIdx.x * 8;
    #pragma unroll
    for (int i = tid; i < NT * IN_F * HID; i += 128) Ws[i] = Wc[i];
    xs[tid] = x[(size_t)n0 * IN_F + tid];
    __syncthreads();
    int c = tid;
    int t = c >> 6, cc = c & 63;
    const float* w = &Ws[t * (IN_F * HID) + cc];
    #pragma unroll
    for (int nd = 0; nd < 8; nd++) {
        float a = 0.f;
        #pragma unroll
        for (int k = 0; k < IN_F; k++) a += xs[nd * IN_F + k] * w[k * HID];
        g_xw[(size_t)(n0 + nd) * 128 + c] = a;
    }
}

// ---------------- gather 1: efeat[t,he] = (1/cnt) * sum_{n in he} xw[n] ----------------
// 16 threads per row (one float4 each); 16 rows per 256-thread block.
__global__ void k_gather1() {
    int idx = blockIdx.x * blockDim.x + threadIdx.x;
    int r = idx >> 4, q = idx & 15;
    if (r >= SB) return;
    int t = (r >= M_HE) ? 1 : 0;
    int he = r - t * M_HE;
    int cnt = g_hB[r];
    int start = g_offB[r];
    float4 a = make_float4(0.f, 0.f, 0.f, 0.f);
    const float4* xw4 = (const float4*)g_xw;
    for (int j = 0; j < cnt; j++) {
        int n = __ldg(&g_idxB[start + j]);
        float4 v = xw4[(size_t)n * 32 + t * 16 + q];
        a.x += v.x; a.y += v.y; a.z += v.z; a.w += v.w;
    }
    float binv = (cnt > 0) ? (1.f / (float)cnt) : 0.f;
    a.x *= binv; a.y *= binv; a.z *= binv; a.w *= binv;
    ((float4*)g_efeat)[(size_t)he * 32 + t * 16 + q] = a;
}

// ---------------- gather 2: acc[t,n] = (1/cnt) * sum_{he of n} efeat[t,he] ----------------
__global__ void k_gather2() {
    int idx = blockIdx.x * blockDim.x + threadIdx.x;
    int r = idx >> 4, q = idx & 15;
    if (r >= SD) return;
    int t = (r >= N_NODES) ? 1 : 0;
    int n = r - t * N_NODES;
    int cnt = g_hD[r];
    int start = g_offD[r];
    float4 a = make_float4(0.f, 0.f, 0.f, 0.f);
    const float4* ef4 = (const float4*)g_efeat;
    for (int j = 0; j < cnt; j++) {
        int he = __ldg(&g_idxD[start + j]);
        float4 v = ef4[(size_t)he * 32 + t * 16 + q];
        a.x += v.x; a.y += v.y; a.z += v.z; a.w += v.w;
    }
    float dinv = (cnt > 0) ? (1.f / (float)cnt) : 0.f;
    a.x *= dinv; a.y *= dinv; a.z *= dinv; a.w *= dinv;
    ((float4*)g_acc)[(size_t)n * 32 + t * 16 + q] = a;
}

// ---------------- mix: u = acc + b_conv ; h = relu(u @ W_mix + b_mix) ----------------
__global__ void k_mix(const float* __restrict__ Wmix, const float* __restrict__ bmix,
                      const float* __restrict__ bconv) {
    extern __shared__ float sm[];
    float* u_s  = sm;                 // 64 * 130
    float* Wm_s = sm + 64 * 130;      // 128 * 64
    float* bm_s = Wm_s + 128 * 64;    // 64
    float* bc_s = bm_s + 64;          // 128
    int tid = threadIdx.x;
    int n0 = blockIdx.x * 64;

    for (int i = tid; i < 128 * 64; i += 256) Wm_s[i] = Wmix[i];
    if (tid < 64)  bm_s[tid] = bmix[tid];
    if (tid < 128) bc_s[tid] = bconv[tid];
    __syncthreads();

    for (int idx = tid; idx < 64 * 128; idx += 256) {
        int nd = idx >> 7, c = idx & 127;
        int n = n0 + nd;
        float u = 0.f;
        if (n < N_NODES) u = g_acc[(size_t)n * 128 + c] + bc_s[c];
        u_s[nd * 130 + c] = u;
    }
    __syncthreads();

    int colg = tid & 15;
    int nodeg = tid >> 4;
    float acc[4][4];
    #pragma unroll
    for (int i = 0; i < 4; i++)
        #pragma unroll
        for (int j = 0; j < 4; j++) acc[i][j] = 0.f;

    for (int k = 0; k < 128; k++) {
        float w0 = Wm_s[k * 64 + colg * 4 + 0];
        float w1 = Wm_s[k * 64 + colg * 4 + 1];
        float w2 = Wm_s[k * 64 + colg * 4 + 2];
        float w3 = Wm_s[k * 64 + colg * 4 + 3];
        #pragma unroll
        for (int i = 0; i < 4; i++) {
            float uv = u_s[(nodeg * 4 + i) * 130 + k];
            acc[i][0] += uv * w0;
            acc[i][1] += uv * w1;
            acc[i][2] += uv * w2;
            acc[i][3] += uv * w3;
        }
    }

    #pragma unroll
    for (int i = 0; i < 4; i++) {
        int n = n0 + nodeg * 4 + i;
        if (n < N_NODES) {
            #pragma unroll
            for (int j = 0; j < 4; j++) {
                int col = colg * 4 + j;
                float h = acc[i][j] + bm_s[col];
                g_h[(size_t)n * 64 + col] = fmaxf(h, 0.f);
            }
        }
    }
}

__device__ __forceinline__ float sigf(float x) { return 1.f / (1.f + expf(-x)); }

#define FMA2(d, a, b) asm("fma.rn.f32x2 %0, %1, %2, %0;" : "+l"(d) : "l"(a), "l"(b))

__device__ __forceinline__ float hsum2(uint64_t v) {
    float lo, hi;
    asm("mov.b64 {%0,%1}, %2;" : "=f"(lo), "=f"(hi) : "l"(v));
    return lo + hi;
}

__device__ __forceinline__ int widx(int row, int k) {
    return (k >> 2) * 768 + row * 4 + (k & 3);
}

// ---------------- GRU + output projection (persistent, f32x2 over k-pairs) ----------------
__global__ __launch_bounds__(256, 1)
void k_gru(const float* __restrict__ hprev,
           const float* __restrict__ Wih, const float* __restrict__ Whh,
           const float* __restrict__ bih, const float* __restrict__ bhh,
           const float* __restrict__ Wout, const float* __restrict__ bout,
           float* __restrict__ out_h, float* __restrict__ out_p) {
    extern __shared__ float sm[];
    float* Wih_s = sm;                    // 12288 (interleaved)
    float* Whh_s = Wih_s + 12288;         // 12288
    float* h_s   = Whh_s + 12288;         // 32*68
    float* hp_s  = h_s  + 32 * 68;
    float* hn_s  = hp_s + 32 * 68;
    float* bih_s = hn_s + 32 * 68;        // 192
    float* bhh_s = bih_s + 192;           // 192
    float* wo_s  = bhh_s + 192;           // 192
    float* bo_s  = wo_s + 192;            // 4

    int tid = threadIdx.x;
    for (int i = tid; i < 192 * 64; i += 256) {
        int row = i >> 6, k = i & 63;
        Wih_s[widx(row, k)] = Wih[i];
        Whh_s[widx(row, k)] = Whh[i];
    }
    if (tid < 192) {
        bih_s[tid] = bih[tid];
        bhh_s[tid] = bhh[tid];
        int j = tid / 3, k = tid % 3;
        wo_s[tid] = Wout[j * 64 + k];
    }
    if (tid < 3) bo_s[tid] = bout[tid];
    __syncthreads();

    const int lane = tid & 31;
    const int wp = tid >> 5;
    const int nbase = wp * 4;
    const int c0 = lane, c1 = lane + 32;

    for (int tile = blockIdx.x; tile < N_NODES / 32; tile += gridDim.x) {
        int n0 = tile * 32;
        for (int i = tid; i < 32 * 64; i += 256) {
            int nd = i >> 6, k = i & 63;
            h_s[nd * 68 + k]  = g_h[(size_t)(n0 + nd) * 64 + k];
            hp_s[nd * 68 + k] = hprev[(size_t)(n0 + nd) * 64 + k];
        }
        __syncthreads();

        uint64_t ai[3][4][2], ah[3][4][2];
        #pragma unroll
        for (int g = 0; g < 3; g++)
            #pragma unroll
            for (int nd = 0; nd < 4; nd++)
                #pragma unroll
                for (int c = 0; c < 2; c++) { ai[g][nd][c] = 0ull; ah[g][nd][c] = 0ull; }

        #pragma unroll 2
        for (int k4 = 0; k4 < 16; k4++) {
            int wb = k4 * 768;
            ulonglong2 wi[2][3], wh[2][3];
            #pragma unroll
            for (int g = 0; g < 3; g++) {
                wi[0][g] = *(const ulonglong2*)&Wih_s[wb + (g * 64 + c0) * 4];
                wi[1][g] = *(const ulonglong2*)&Wih_s[wb + (g * 64 + c1) * 4];
                wh[0][g] = *(const ulonglong2*)&Whh_s[wb + (g * 64 + c0) * 4];
                wh[1][g] = *(const ulonglong2*)&Whh_s[wb + (g * 64 + c1) * 4];
            }
            #pragma unroll
            for (int nd = 0; nd < 4; nd++) {
                ulonglong2 hv = *(const ulonglong2*)&h_s[(nbase + nd) * 68 + k4 * 4];
                ulonglong2 pv = *(const ulonglong2*)&hp_s[(nbase + nd) * 68 + k4 * 4];
                #pragma unroll
                for (int c = 0; c < 2; c++) {
                    #pragma unroll
                    for (int g = 0; g < 3; g++) {
                        FMA2(ai[g][nd][c], hv.x, wi[c][g].x);
                        FMA2(ai[g][nd][c], hv.y, wi[c][g].y);
                        FMA2(ah[g][nd][c], pv.x, wh[c][g].x);
                        FMA2(ah[g][nd][c], pv.y, wh[c][g].y);
                    }
                }
            }
        }

        #pragma unroll
        for (int nd = 0; nd < 4; nd++) {
            #pragma unroll
            for (int c = 0; c < 2; c++) {
                int col = c ? c1 : c0;
                int n = n0 + nbase + nd;
                float ir = hsum2(ai[0][nd][c]) + bih_s[col];
                float iz = hsum2(ai[1][nd][c]) + bih_s[64 + col];
                float in_ = hsum2(ai[2][nd][c]) + bih_s[128 + col];
                float hr = hsum2(ah[0][nd][c]) + bhh_s[col];
                float hz = hsum2(ah[1][nd][c]) + bhh_s[64 + col];
                float hn = hsum2(ah[2][nd][c]) + bhh_s[128 + col];
                float r = sigf(ir + hr);
                float z = sigf(iz + hz);
                float nn = tanhf(in_ + r * hn);
                float hp = hp_s[(nbase + nd) * 68 + col];
                float hx = (1.f - z) * nn + z * hp;
                out_h[(size_t)n * 64 + col] = hx;
                hn_s[(nbase + nd) * 68 + col] = hx;
            }
        }
        __syncthreads();

        if (tid < 96) {
            int nd = tid / 3, k = tid % 3;
            float a = bo_s[k];
            #pragma unroll
            for (int j = 0; j < 64; j++) a += hn_s[nd * 68 + j] * wo_s[j * 3 + k];
            out_p[(size_t)(n0 + nd) * 3 + k] = a;
        }
        __syncthreads();
    }
}

extern "C" void kernel_launch(void* const* d_in, const int* in_sizes, int n_in,
                              void* d_out, int out_size) {
    const float* x       = (const float*)d_in[0];
    const float* h_prev  = (const float*)d_in[1];
    const int* en        = (const int*)d_in[2];
    const int* eh        = (const int*)d_in[3];
    const int* ea        = (const int*)d_in[4];
    const float* W_conv  = (const float*)d_in[5];
    const float* b_conv  = (const float*)d_in[6];
    const float* W_mix   = (const float*)d_in[7];
    const float* b_mix   = (const float*)d_in[8];
    const float* W_ih    = (const float*)d_in[9];
    const float* W_hh    = (const float*)d_in[10];
    const float* b_ih    = (const float*)d_in[11];
    const float* b_hh    = (const float*)d_in[12];
    const float* W_out   = (const float*)d_in[13];
    const float* b_out   = (const float*)d_in[14];
    float* out = (float*)d_out;
    float* out_h = out;
    float* out_p = out + (size_t)N_NODES * 64;

    static const int mix_smem = (64 * 130 + 128 * 64 + 64 + 128) * 4;
    static const int gru_smem = (12288 * 2 + 32 * 68 * 3 + 192 * 3 + 4) * 4;
    cudaFuncSetAttribute(k_mix, cudaFuncAttributeMaxDynamicSharedMemorySize, mix_smem);
    cudaFuncSetAttribute(k_gru, cudaFuncAttributeMaxDynamicSharedMemorySize, gru_smem);

    // sort phase
    k_zero_hist<<<(SB + 255) / 256, 256>>>();
    k_hist<<<(NE + 255) / 256, 256>>>(en, eh, ea);
    k_scan_local<<<NBB, 256>>>(0);
    k_scan_local<<<NBD, 256>>>(1);
    k_scan_tops<<<1, 512>>>(0);
    k_scan_tops<<<1, 512>>>(1);
    k_scan_add<<<(SB + 255) / 256, 256>>>(0);
    k_scan_add<<<(SD + 255) / 256, 256>>>(1);
    k_place<<<(NE + 255) / 256, 256>>>(en, eh, ea);

    // dense projection (overlaps nothing but is independent of sort)
    k_xw<<<N_NODES / 8, 128>>>(x, W_conv);

    // gather phases (no atomics, no zeroing)
    k_gather1<<<(SB * 16 + 255) / 256, 256>>>();
    k_gather2<<<(SD * 16 + 255) / 256, 256>>>();

    k_mix<<<(N_NODES + 63) / 64, 256, mix_smem>>>(W_mix, b_mix, b_conv);
    k_gru<<<152, 256, gru_smem>>>(h_prev, W_ih, W_hh, b_ih, b_hh,
                                  W_out, b_out, out_h, out_p);
}

// round 5
// speedup vs baseline: 1.9948x; 1.1285x over previous
#include <cuda_runtime.h>
#include <cuda_fp16.h>
#include <cstdint>

#define N_NODES 100000
#define M_HE    200000
#define NE      2000000
#define IN_F    16
#define HID     64
#define NT      2

#define SB (NT * M_HE)     // 400000 hyperedge-type rows
#define SD (NT * N_NODES)  // 200000 node-type rows
#define NBB ((SB + 1023) / 1024)   // 391
#define NBD ((SD + 1023) / 1024)   // 196

// ---------------- scratch (no allocations allowed) ----------------
__device__ __align__(16) __half g_xw_h[(size_t)N_NODES * 128];   // [n][t*64+c] fp16
__device__ __align__(16) __half g_efeat_h[(size_t)M_HE * 128];   // [he][t*64+c] fp16
__device__ __align__(16) float  g_acc[(size_t)N_NODES * 128];    // [n][t*64+c] fp32
__device__ __align__(16) float  g_h[(size_t)N_NODES * HID];
__device__ int g_hB[SB], g_hD[SD];        // histograms (counts)
__device__ int g_offB[SB], g_offD[SD];    // CSR row starts
__device__ int g_curB[SB], g_curD[SD];    // placement cursors
__device__ int g_bsum[1024];              // block sums: [0..511]=B, [512..1023]=D
__device__ int g_idxB[NE];                // he-sorted: node ids
__device__ int g_idxD[NE];                // node-sorted: hyperedge ids

// ---------------- zero histograms ----------------
__global__ void k_zero_hist() {
    int i = blockIdx.x * blockDim.x + threadIdx.x;
    if (i < SB) g_hB[i] = 0;
    if (i < SD) g_hD[i] = 0;
}

// ---------------- histogram ----------------
__global__ void k_hist(const int* __restrict__ en, const int* __restrict__ eh,
                       const int* __restrict__ ea) {
    int i = blockIdx.x * blockDim.x + threadIdx.x;
    if (i >= NE) return;
    int t = ea[i];
    atomicAdd(&g_hB[t * M_HE + eh[i]], 1);
    atomicAdd(&g_hD[t * N_NODES + en[i]], 1);
}

// ---------------- scan step 1: per-block (1024 elems) exclusive scan ----------------
__global__ void k_scan_local(int which) {
    const int n   = which ? SD : SB;
    const int* in = which ? g_hD : g_hB;
    int* out      = which ? g_offD : g_offB;
    int* sums     = g_bsum + which * 512;
    int tid = threadIdx.x;
    int base = blockIdx.x * 1024 + tid * 4;
    int v0 = (base + 0 < n) ? in[base + 0] : 0;
    int v1 = (base + 1 < n) ? in[base + 1] : 0;
    int v2 = (base + 2 < n) ? in[base + 2] : 0;
    int v3 = (base + 3 < n) ? in[base + 3] : 0;
    int s = v0 + v1 + v2 + v3;
    __shared__ int sh[256];
    sh[tid] = s;
    __syncthreads();
    for (int d = 1; d < 256; d <<= 1) {
        int v = (tid >= d) ? sh[tid - d] : 0;
        __syncthreads();
        sh[tid] += v;
        __syncthreads();
    }
    int excl = sh[tid] - s;
    if (base + 0 < n) out[base + 0] = excl;
    if (base + 1 < n) out[base + 1] = excl + v0;
    if (base + 2 < n) out[base + 2] = excl + v0 + v1;
    if (base + 3 < n) out[base + 3] = excl + v0 + v1 + v2;
    if (tid == 255) sums[blockIdx.x] = excl + s;
}

// ---------------- scan step 2: exclusive scan of block sums ----------------
__global__ void k_scan_tops(int which) {
    const int nb = which ? NBD : NBB;
    int* sums = g_bsum + which * 512;
    int tid = threadIdx.x;  // 512 threads
    __shared__ int sh[512];
    int s = (tid < nb) ? sums[tid] : 0;
    sh[tid] = s;
    __syncthreads();
    for (int d = 1; d < 512; d <<= 1) {
        int v = (tid >= d) ? sh[tid - d] : 0;
        __syncthreads();
        sh[tid] += v;
        __syncthreads();
    }
    if (tid < nb) sums[tid] = sh[tid] - s;
}

// ---------------- scan step 3: add block offsets; init cursors ----------------
__global__ void k_scan_add(int which) {
    const int n = which ? SD : SB;
    int* out    = which ? g_offD : g_offB;
    int* cur    = which ? g_curD : g_curB;
    const int* sums = g_bsum + which * 512;
    int i = blockIdx.x * blockDim.x + threadIdx.x;
    if (i >= n) return;
    int v = out[i] + sums[i >> 10];
    out[i] = v;
    cur[i] = v;
}

// ---------------- placement: counting-sort scatter of incidences ----------------
__global__ void k_place(const int* __restrict__ en, const int* __restrict__ eh,
                        const int* __restrict__ ea) {
    int i = blockIdx.x * blockDim.x + threadIdx.x;
    if (i >= NE) return;
    int t = ea[i], n = en[i], he = eh[i];
    int pb = atomicAdd(&g_curB[t * M_HE + he], 1);
    g_idxB[pb] = n;
    int pd = atomicAdd(&g_curD[t * N_NODES + n], 1);
    g_idxD[pd] = he;
}

// ---------------- xw = x @ W_conv[t] for both t (fp16 out) ----------------
__global__ void k_xw(const float* __restrict__ x, const float* __restrict__ Wc) {
    __shared__ float Ws[NT * IN_F * HID];
    __shared__ float xs[8 * IN_F];
    int tid = threadIdx.x;
    int n0 = blockIdx.x * 8;
    #pragma unroll
    for (int i = tid; i < NT * IN_F * HID; i += 128) Ws[i] = Wc[i];
    xs[tid] = x[(size_t)n0 * IN_F + tid];
    __syncthreads();
    int c = tid;
    int t = c >> 6, cc = c & 63;
    const float* w = &Ws[t * (IN_F * HID) + cc];
    #pragma unroll
    for (int nd = 0; nd < 8; nd++) {
        float a = 0.f;
        #pragma unroll
        for (int k = 0; k < IN_F; k++) a += xs[nd * IN_F + k] * w[k * HID];
        float a_hi = __shfl_down_sync(0xffffffffu, a, 1);
        if ((c & 1) == 0) {
            __half2 hv = __floats2half2_rn(a, a_hi);
            ((__half2*)g_xw_h)[((size_t)(n0 + nd) * 128 + c) >> 1] = hv;
        }
    }
}

__device__ __forceinline__ void accum8(float* s, uint4 v) {
    const __half2* h = (const __half2*)&v;
    #pragma unroll
    for (int i = 0; i < 4; i++) {
        float2 f = __half22float2(h[i]);
        s[2 * i]     += f.x;
        s[2 * i + 1] += f.y;
    }
}

// ---------------- gather 1: efeat[t,he] = (1/cnt) * sum xw_h[n] ----------------
// 8 threads per row, each 16B (8 halves); unroll-2 for MLP.
__global__ void k_gather1() {
    int idx = blockIdx.x * blockDim.x + threadIdx.x;
    int r = idx >> 3, q = idx & 7;
    if (r >= SB) return;
    int t = (r >= M_HE) ? 1 : 0;
    int he = r - t * M_HE;
    int cnt = g_hB[r];
    int start = g_offB[r];
    const uint4* xw4 = (const uint4*)g_xw_h;   // 16 uint4 per node row
    int off = t * 8 + q;
    float s[8] = {0.f, 0.f, 0.f, 0.f, 0.f, 0.f, 0.f, 0.f};
    int j = 0;
    for (; j + 2 <= cnt; j += 2) {
        int n0 = __ldg(&g_idxB[start + j]);
        int n1 = __ldg(&g_idxB[start + j + 1]);
        uint4 v0 = xw4[(size_t)n0 * 16 + off];
        uint4 v1 = xw4[(size_t)n1 * 16 + off];
        accum8(s, v0);
        accum8(s, v1);
    }
    if (j < cnt) {
        int n = __ldg(&g_idxB[start + j]);
        accum8(s, xw4[(size_t)n * 16 + off]);
    }
    float binv = (cnt > 0) ? (1.f / (float)cnt) : 0.f;
    uint4 outv;
    __half2* oh = (__half2*)&outv;
    #pragma unroll
    for (int i = 0; i < 4; i++)
        oh[i] = __floats2half2_rn(s[2 * i] * binv, s[2 * i + 1] * binv);
    ((uint4*)g_efeat_h)[(size_t)he * 16 + t * 8 + q] = outv;
}

// ---------------- gather 2: acc[t,n] = (1/cnt) * sum efeat_h[he] (fp32 out) ----------------
__global__ void k_gather2() {
    int idx = blockIdx.x * blockDim.x + threadIdx.x;
    int r = idx >> 3, q = idx & 7;
    if (r >= SD) return;
    int t = (r >= N_NODES) ? 1 : 0;
    int n = r - t * N_NODES;
    int cnt = g_hD[r];
    int start = g_offD[r];
    const uint4* ef4 = (const uint4*)g_efeat_h;
    int off = t * 8 + q;
    float s[8] = {0.f, 0.f, 0.f, 0.f, 0.f, 0.f, 0.f, 0.f};
    int j = 0;
    for (; j + 2 <= cnt; j += 2) {
        int h0 = __ldg(&g_idxD[start + j]);
        int h1 = __ldg(&g_idxD[start + j + 1]);
        uint4 v0 = ef4[(size_t)h0 * 16 + off];
        uint4 v1 = ef4[(size_t)h1 * 16 + off];
        accum8(s, v0);
        accum8(s, v1);
    }
    if (j < cnt) {
        int he = __ldg(&g_idxD[start + j]);
        accum8(s, ef4[(size_t)he * 16 + off]);
    }
    float dinv = (cnt > 0) ? (1.f / (float)cnt) : 0.f;
    float4 o0 = make_float4(s[0] * dinv, s[1] * dinv, s[2] * dinv, s[3] * dinv);
    float4 o1 = make_float4(s[4] * dinv, s[5] * dinv, s[6] * dinv, s[7] * dinv);
    ((float4*)g_acc)[(size_t)n * 32 + t * 16 + q * 2]     = o0;
    ((float4*)g_acc)[(size_t)n * 32 + t * 16 + q * 2 + 1] = o1;
}

#define FMA2(d, a, b) asm("fma.rn.f32x2 %0, %1, %2, %0;" : "+l"(d) : "l"(a), "l"(b))

__device__ __forceinline__ float hsum2(uint64_t v) {
    float lo, hi;
    asm("mov.b64 {%0,%1}, %2;" : "=f"(lo), "=f"(hi) : "l"(v));
    return lo + hi;
}

// ---------------- mix: u = acc + b_conv ; h = relu(u @ W_mix + b_mix) ----------------
// f32x2 packed over k. W pre-interleaved into float2 pairs (k, k+1).
// Thread: 4 nodes x 4 strided cols (colg, colg+16, colg+32, colg+48).
__global__ void k_mix(const float* __restrict__ Wmix, const float* __restrict__ bmix,
                      const float* __restrict__ bconv) {
    extern __shared__ float sm[];
    float* u_s  = sm;                 // 64 * 130 = 8320
    float* Wp   = sm + 8320;          // 8192: float2[64 k2][64 c]
    float* bm_s = Wp + 8192;          // 64
    float* bc_s = bm_s + 64;          // 128
    int tid = threadIdx.x;
    int n0 = blockIdx.x * 64;

    for (int i = tid; i < 4096; i += 256) {
        int k2 = i >> 6, c = i & 63;
        Wp[i * 2]     = Wmix[(2 * k2) * 64 + c];
        Wp[i * 2 + 1] = Wmix[(2 * k2 + 1) * 64 + c];
    }
    if (tid < 64)  bm_s[tid] = bmix[tid];
    if (tid < 128) bc_s[tid] = bconv[tid];
    __syncthreads();

    for (int idx = tid; idx < 64 * 128; idx += 256) {
        int nd = idx >> 7, c = idx & 127;
        int n = n0 + nd;
        float u = 0.f;
        if (n < N_NODES) u = g_acc[(size_t)n * 128 + c] + bc_s[c];
        u_s[nd * 130 + c] = u;
    }
    __syncthreads();

    int colg = tid & 15;
    int nodeg = tid >> 4;
    uint64_t acc2[4][4];
    #pragma unroll
    for (int i = 0; i < 4; i++)
        #pragma unroll
        for (int j = 0; j < 4; j++) acc2[i][j] = 0ull;

    #pragma unroll 4
    for (int k2 = 0; k2 < 64; k2++) {
        uint64_t w[4];
        #pragma unroll
        for (int j = 0; j < 4; j++)
            w[j] = *(const uint64_t*)&Wp[(k2 * 64 + colg + 16 * j) * 2];
        #pragma unroll
        for (int i = 0; i < 4; i++) {
            uint64_t uv = *(const uint64_t*)&u_s[(nodeg * 4 + i) * 130 + k2 * 2];
            #pragma unroll
            for (int j = 0; j < 4; j++) FMA2(acc2[i][j], uv, w[j]);
        }
    }

    #pragma unroll
    for (int i = 0; i < 4; i++) {
        int n = n0 + nodeg * 4 + i;
        if (n < N_NODES) {
            #pragma unroll
            for (int j = 0; j < 4; j++) {
                int col = colg + 16 * j;
                float h = hsum2(acc2[i][j]) + bm_s[col];
                g_h[(size_t)n * 64 + col] = fmaxf(h, 0.f);
            }
        }
    }
}

__device__ __forceinline__ float sigf(float x) { return 1.f / (1.f + expf(-x)); }

__device__ __forceinline__ int widx(int row, int k) {
    return (k >> 2) * 768 + row * 4 + (k & 3);
}

// ---------------- GRU + output projection (persistent, f32x2 over k-pairs) ----------------
__global__ __launch_bounds__(256, 1)
void k_gru(const float* __restrict__ hprev,
           const float* __restrict__ Wih, const float* __restrict__ Whh,
           const float* __restrict__ bih, const float* __restrict__ bhh,
           const float* __restrict__ Wout, const float* __restrict__ bout,
           float* __restrict__ out_h, float* __restrict__ out_p) {
    extern __shared__ float sm[];
    float* Wih_s = sm;                    // 12288 (interleaved)
    float* Whh_s = Wih_s + 12288;         // 12288
    float* h_s   = Whh_s + 12288;         // 32*68
    float* hp_s  = h_s  + 32 * 68;
    float* hn_s  = hp_s + 32 * 68;
    float* bih_s = hn_s + 32 * 68;        // 192
    float* bhh_s = bih_s + 192;           // 192
    float* wo_s  = bhh_s + 192;           // 192
    float* bo_s  = wo_s + 192;            // 4

    int tid = threadIdx.x;
    for (int i = tid; i < 192 * 64; i += 256) {
        int row = i >> 6, k = i & 63;
        Wih_s[widx(row, k)] = Wih[i];
        Whh_s[widx(row, k)] = Whh[i];
    }
    if (tid < 192) {
        bih_s[tid] = bih[tid];
        bhh_s[tid] = bhh[tid];
        int j = tid / 3, k = tid % 3;
        wo_s[tid] = Wout[j * 64 + k];
    }
    if (tid < 3) bo_s[tid] = bout[tid];
    __syncthreads();

    const int lane = tid & 31;
    const int wp = tid >> 5;
    const int nbase = wp * 4;
    const int c0 = lane, c1 = lane + 32;

    for (int tile = blockIdx.x; tile < N_NODES / 32; tile += gridDim.x) {
        int n0 = tile * 32;
        for (int i = tid; i < 32 * 64; i += 256) {
            int nd = i >> 6, k = i & 63;
            h_s[nd * 68 + k]  = g_h[(size_t)(n0 + nd) * 64 + k];
            hp_s[nd * 68 + k] = hprev[(size_t)(n0 + nd) * 64 + k];
        }
        __syncthreads();

        uint64_t ai[3][4][2], ah[3][4][2];
        #pragma unroll
        for (int g = 0; g < 3; g++)
            #pragma unroll
            for (int nd = 0; nd < 4; nd++)
                #pragma unroll
                for (int c = 0; c < 2; c++) { ai[g][nd][c] = 0ull; ah[g][nd][c] = 0ull; }

        #pragma unroll 2
        for (int k4 = 0; k4 < 16; k4++) {
            int wb = k4 * 768;
            ulonglong2 wi[2][3], wh[2][3];
            #pragma unroll
            for (int g = 0; g < 3; g++) {
                wi[0][g] = *(const ulonglong2*)&Wih_s[wb + (g * 64 + c0) * 4];
                wi[1][g] = *(const ulonglong2*)&Wih_s[wb + (g * 64 + c1) * 4];
                wh[0][g] = *(const ulonglong2*)&Whh_s[wb + (g * 64 + c0) * 4];
                wh[1][g] = *(const ulonglong2*)&Whh_s[wb + (g * 64 + c1) * 4];
            }
            #pragma unroll
            for (int nd = 0; nd < 4; nd++) {
                ulonglong2 hv = *(const ulonglong2*)&h_s[(nbase + nd) * 68 + k4 * 4];
                ulonglong2 pv = *(const ulonglong2*)&hp_s[(nbase + nd) * 68 + k4 * 4];
                #pragma unroll
                for (int c = 0; c < 2; c++) {
                    #pragma unroll
                    for (int g = 0; g < 3; g++) {
                        FMA2(ai[g][nd][c], hv.x, wi[c][g].x);
                        FMA2(ai[g][nd][c], hv.y, wi[c][g].y);
                        FMA2(ah[g][nd][c], pv.x, wh[c][g].x);
                        FMA2(ah[g][nd][c], pv.y, wh[c][g].y);
                    }
                }
            }
        }

        #pragma unroll
        for (int nd = 0; nd < 4; nd++) {
            #pragma unroll
            for (int c = 0; c < 2; c++) {
                int col = c ? c1 : c0;
                int n = n0 + nbase + nd;
                float ir = hsum2(ai[0][nd][c]) + bih_s[col];
                float iz = hsum2(ai[1][nd][c]) + bih_s[64 + col];
                float in_ = hsum2(ai[2][nd][c]) + bih_s[128 + col];
                float hr = hsum2(ah[0][nd][c]) + bhh_s[col];
                float hz = hsum2(ah[1][nd][c]) + bhh_s[64 + col];
                float hn = hsum2(ah[2][nd][c]) + bhh_s[128 + col];
                float r = sigf(ir + hr);
                float z = sigf(iz + hz);
                float nn = tanhf(in_ + r * hn);
                float hp = hp_s[(nbase + nd) * 68 + col];
                float hx = (1.f - z) * nn + z * hp;
                out_h[(size_t)n * 64 + col] = hx;
                hn_s[(nbase + nd) * 68 + col] = hx;
            }
        }
        __syncthreads();

        if (tid < 96) {
            int nd = tid / 3, k = tid % 3;
            float a = bo_s[k];
            #pragma unroll
            for (int j = 0; j < 64; j++) a += hn_s[nd * 68 + j] * wo_s[j * 3 + k];
            out_p[(size_t)(n0 + nd) * 3 + k] = a;
        }
        __syncthreads();
    }
}

extern "C" void kernel_launch(void* const* d_in, const int* in_sizes, int n_in,
                              void* d_out, int out_size) {
    const float* x       = (const float*)d_in[0];
    const float* h_prev  = (const float*)d_in[1];
    const int* en        = (const int*)d_in[2];
    const int* eh        = (const int*)d_in[3];
    const int* ea        = (const int*)d_in[4];
    const float* W_conv  = (const float*)d_in[5];
    const float* b_conv  = (const float*)d_in[6];
    const float* W_mix   = (const float*)d_in[7];
    const float* b_mix   = (const float*)d_in[8];
    const float* W_ih    = (const float*)d_in[9];
    const float* W_hh    = (const float*)d_in[10];
    const float* b_ih    = (const float*)d_in[11];
    const float* b_hh    = (const float*)d_in[12];
    const float* W_out   = (const float*)d_in[13];
    const float* b_out   = (const float*)d_in[14];
    float* out = (float*)d_out;
    float* out_h = out;
    float* out_p = out + (size_t)N_NODES * 64;

    static const int mix_smem = (8320 + 8192 + 64 + 128) * 4;
    static const int gru_smem = (12288 * 2 + 32 * 68 * 3 + 192 * 3 + 4) * 4;
    cudaFuncSetAttribute(k_mix, cudaFuncAttributeMaxDynamicSharedMemorySize, mix_smem);
    cudaFuncSetAttribute(k_gru, cudaFuncAttributeMaxDynamicSharedMemorySize, gru_smem);

    // sort phase
    k_zero_hist<<<(SB + 255) / 256, 256>>>();
    k_hist<<<(NE + 255) / 256, 256>>>(en, eh, ea);
    k_scan_local<<<NBB, 256>>>(0);
    k_scan_local<<<NBD, 256>>>(1);
    k_scan_tops<<<1, 512>>>(0);
    k_scan_tops<<<1, 512>>>(1);
    k_scan_add<<<(SB + 255) / 256, 256>>>(0);
    k_scan_add<<<(SD + 255) / 256, 256>>>(1);
    k_place<<<(NE + 255) / 256, 256>>>(en, eh, ea);

    // dense projection
    k_xw<<<N_NODES / 8, 128>>>(x, W_conv);

    // gather phases
    k_gather1<<<(SB * 8 + 255) / 256, 256>>>();
    k_gather2<<<(SD * 8 + 255) / 256, 256>>>();

    k_mix<<<(N_NODES + 63) / 64, 256, mix_smem>>>(W_mix, b_mix, b_conv);
    k_gru<<<152, 256, gru_smem>>>(h_prev, W_ih, W_hh, b_ih, b_hh,
                                  W_out, b_out, out_h, out_p);
}

// round 6
// speedup vs baseline: 2.3638x; 1.1849x over previous
#include <cuda_runtime.h>
#include <cuda_fp16.h>
#include <cstdint>

#define N_NODES 100000
#define M_HE    200000
#define NE      2000000
#define IN_F    16
#define HID     64
#define NT      2

#define SB (NT * M_HE)     // 400000 hyperedge-type rows
#define SD (NT * N_NODES)  // 200000 node-type rows
#define NBB ((SB + 1023) / 1024)   // 391
#define NBD ((SD + 1023) / 1024)   // 196
#define TILES ((N_NODES + 63) / 64)  // 1563

// ---------------- scratch (no allocations allowed) ----------------
__device__ __align__(16) __half g_xw_h[(size_t)N_NODES * 128];   // [n][t*64+c] fp16
__device__ __align__(16) __half g_efeat_h[(size_t)M_HE * 128];   // [he][t*64+c] fp16
__device__ __align__(16) float  g_acc[(size_t)N_NODES * 128];    // [n][t*64+c] fp32
__device__ __align__(16) float  g_h[(size_t)N_NODES * HID];
__device__ int g_hB[SB], g_hD[SD];        // histograms (counts)
__device__ int g_offB[SB], g_offD[SD];    // CSR row starts
__device__ int g_curB[SB], g_curD[SD];    // placement cursors
__device__ int g_bsum[1024];              // block sums: [0..511]=B, [512..1023]=D
__device__ int g_idxB[NE];                // he-sorted: node ids
__device__ int g_idxD[NE];                // node-sorted: hyperedge ids

// ---------------- zero histograms ----------------
__global__ void k_zero_hist() {
    int i = blockIdx.x * blockDim.x + threadIdx.x;
    if (i < SB) g_hB[i] = 0;
    if (i < SD) g_hD[i] = 0;
}

// ---------------- histogram ----------------
__global__ void k_hist(const int* __restrict__ en, const int* __restrict__ eh,
                       const int* __restrict__ ea) {
    int i = blockIdx.x * blockDim.x + threadIdx.x;
    if (i >= NE) return;
    int t = ea[i];
    atomicAdd(&g_hB[t * M_HE + eh[i]], 1);
    atomicAdd(&g_hD[t * N_NODES + en[i]], 1);
}

// ---------------- scan step 1: per-block (1024 elems) exclusive scan ----------------
__global__ void k_scan_local(int which) {
    const int n   = which ? SD : SB;
    const int* in = which ? g_hD : g_hB;
    int* out      = which ? g_offD : g_offB;
    int* sums     = g_bsum + which * 512;
    int tid = threadIdx.x;
    int base = blockIdx.x * 1024 + tid * 4;
    int v0 = (base + 0 < n) ? in[base + 0] : 0;
    int v1 = (base + 1 < n) ? in[base + 1] : 0;
    int v2 = (base + 2 < n) ? in[base + 2] : 0;
    int v3 = (base + 3 < n) ? in[base + 3] : 0;
    int s = v0 + v1 + v2 + v3;
    __shared__ int sh[256];
    sh[tid] = s;
    __syncthreads();
    for (int d = 1; d < 256; d <<= 1) {
        int v = (tid >= d) ? sh[tid - d] : 0;
        __syncthreads();
        sh[tid] += v;
        __syncthreads();
    }
    int excl = sh[tid] - s;
    if (base + 0 < n) out[base + 0] = excl;
    if (base + 1 < n) out[base + 1] = excl + v0;
    if (base + 2 < n) out[base + 2] = excl + v0 + v1;
    if (base + 3 < n) out[base + 3] = excl + v0 + v1 + v2;
    if (tid == 255) sums[blockIdx.x] = excl + s;
}

// ---------------- scan step 2: exclusive scan of block sums ----------------
__global__ void k_scan_tops(int which) {
    const int nb = which ? NBD : NBB;
    int* sums = g_bsum + which * 512;
    int tid = threadIdx.x;  // 512 threads
    __shared__ int sh[512];
    int s = (tid < nb) ? sums[tid] : 0;
    sh[tid] = s;
    __syncthreads();
    for (int d = 1; d < 512; d <<= 1) {
        int v = (tid >= d) ? sh[tid - d] : 0;
        __syncthreads();
        sh[tid] += v;
        __syncthreads();
    }
    if (tid < nb) sums[tid] = sh[tid] - s;
}

// ---------------- scan step 3: add block offsets; init cursors ----------------
__global__ void k_scan_add(int which) {
    const int n = which ? SD : SB;
    int* out    = which ? g_offD : g_offB;
    int* cur    = which ? g_curD : g_curB;
    const int* sums = g_bsum + which * 512;
    int i = blockIdx.x * blockDim.x + threadIdx.x;
    if (i >= n) return;
    int v = out[i] + sums[i >> 10];
    out[i] = v;
    cur[i] = v;
}

// ---------------- placement: counting-sort scatter of incidences ----------------
__global__ void k_place(const int* __restrict__ en, const int* __restrict__ eh,
                        const int* __restrict__ ea) {
    int i = blockIdx.x * blockDim.x + threadIdx.x;
    if (i >= NE) return;
    int t = ea[i], n = en[i], he = eh[i];
    int pb = atomicAdd(&g_curB[t * M_HE + he], 1);
    g_idxB[pb] = n;
    int pd = atomicAdd(&g_curD[t * N_NODES + n], 1);
    g_idxD[pd] = he;
}

// ---------------- xw = x @ W_conv[t] for both t (fp16 out) ----------------
__global__ void k_xw(const float* __restrict__ x, const float* __restrict__ Wc) {
    __shared__ float Ws[NT * IN_F * HID];
    __shared__ float xs[8 * IN_F];
    int tid = threadIdx.x;
    int n0 = blockIdx.x * 8;
    #pragma unroll
    for (int i = tid; i < NT * IN_F * HID; i += 128) Ws[i] = Wc[i];
    xs[tid] = x[(size_t)n0 * IN_F + tid];
    __syncthreads();
    int c = tid;
    int t = c >> 6, cc = c & 63;
    const float* w = &Ws[t * (IN_F * HID) + cc];
    #pragma unroll
    for (int nd = 0; nd < 8; nd++) {
        float a = 0.f;
        #pragma unroll
        for (int k = 0; k < IN_F; k++) a += xs[nd * IN_F + k] * w[k * HID];
        float a_hi = __shfl_down_sync(0xffffffffu, a, 1);
        if ((c & 1) == 0) {
            __half2 hv = __floats2half2_rn(a, a_hi);
            ((__half2*)g_xw_h)[((size_t)(n0 + nd) * 128 + c) >> 1] = hv;
        }
    }
}

__device__ __forceinline__ void accum8(float* s, uint4 v) {
    const __half2* h = (const __half2*)&v;
    #pragma unroll
    for (int i = 0; i < 4; i++) {
        float2 f = __half22float2(h[i]);
        s[2 * i]     += f.x;
        s[2 * i + 1] += f.y;
    }
}

// ---------------- gather 1: efeat[t,he] = (1/cnt) * sum xw_h[n] ----------------
__global__ void k_gather1() {
    int idx = blockIdx.x * blockDim.x + threadIdx.x;
    int r = idx >> 3, q = idx & 7;
    if (r >= SB) return;
    int t = (r >= M_HE) ? 1 : 0;
    int he = r - t * M_HE;
    int cnt = g_hB[r];
    int start = g_offB[r];
    const uint4* xw4 = (const uint4*)g_xw_h;   // 16 uint4 per node row
    int off = t * 8 + q;
    float s[8] = {0.f, 0.f, 0.f, 0.f, 0.f, 0.f, 0.f, 0.f};
    int j = 0;
    for (; j + 2 <= cnt; j += 2) {
        int n0 = __ldg(&g_idxB[start + j]);
        int n1 = __ldg(&g_idxB[start + j + 1]);
        uint4 v0 = xw4[(size_t)n0 * 16 + off];
        uint4 v1 = xw4[(size_t)n1 * 16 + off];
        accum8(s, v0);
        accum8(s, v1);
    }
    if (j < cnt) {
        int n = __ldg(&g_idxB[start + j]);
        accum8(s, xw4[(size_t)n * 16 + off]);
    }
    float binv = (cnt > 0) ? (1.f / (float)cnt) : 0.f;
    uint4 outv;
    __half2* oh = (__half2*)&outv;
    #pragma unroll
    for (int i = 0; i < 4; i++)
        oh[i] = __floats2half2_rn(s[2 * i] * binv, s[2 * i + 1] * binv);
    ((uint4*)g_efeat_h)[(size_t)he * 16 + t * 8 + q] = outv;
}

// ---------------- gather 2: acc[t,n] = (1/cnt) * sum efeat_h[he] (fp32 out) ----------------
__global__ void k_gather2() {
    int idx = blockIdx.x * blockDim.x + threadIdx.x;
    int r = idx >> 3, q = idx & 7;
    if (r >= SD) return;
    int t = (r >= N_NODES) ? 1 : 0;
    int n = r - t * N_NODES;
    int cnt = g_hD[r];
    int start = g_offD[r];
    const uint4* ef4 = (const uint4*)g_efeat_h;
    int off = t * 8 + q;
    float s[8] = {0.f, 0.f, 0.f, 0.f, 0.f, 0.f, 0.f, 0.f};
    int j = 0;
    for (; j + 2 <= cnt; j += 2) {
        int h0 = __ldg(&g_idxD[start + j]);
        int h1 = __ldg(&g_idxD[start + j + 1]);
        uint4 v0 = ef4[(size_t)h0 * 16 + off];
        uint4 v1 = ef4[(size_t)h1 * 16 + off];
        accum8(s, v0);
        accum8(s, v1);
    }
    if (j < cnt) {
        int he = __ldg(&g_idxD[start + j]);
        accum8(s, ef4[(size_t)he * 16 + off]);
    }
    float dinv = (cnt > 0) ? (1.f / (float)cnt) : 0.f;
    float4 o0 = make_float4(s[0] * dinv, s[1] * dinv, s[2] * dinv, s[3] * dinv);
    float4 o1 = make_float4(s[4] * dinv, s[5] * dinv, s[6] * dinv, s[7] * dinv);
    ((float4*)g_acc)[(size_t)n * 32 + t * 16 + q * 2]     = o0;
    ((float4*)g_acc)[(size_t)n * 32 + t * 16 + q * 2 + 1] = o1;
}

#define FMA2(d, a, b) asm("fma.rn.f32x2 %0, %1, %2, %0;" : "+l"(d) : "l"(a), "l"(b))

__device__ __forceinline__ float hsum2(uint64_t v) {
    float lo, hi;
    asm("mov.b64 {%0,%1}, %2;" : "=f"(lo), "=f"(hi) : "l"(v));
    return lo + hi;
}

// ---------------- mix: u = acc + b_conv ; h = relu(u @ W_mix + b_mix) ----------------
__global__ void k_mix(const float* __restrict__ Wmix, const float* __restrict__ bmix,
                      const float* __restrict__ bconv) {
    extern __shared__ float sm[];
    float* u_s  = sm;                 // 64 * 130 = 8320
    float* Wp   = sm + 8320;          // 8192: float2[64 k2][64 c]
    float* bm_s = Wp + 8192;          // 64
    float* bc_s = bm_s + 64;          // 128
    int tid = threadIdx.x;
    int n0 = blockIdx.x * 64;

    for (int i = tid; i < 4096; i += 256) {
        int k2 = i >> 6, c = i & 63;
        Wp[i * 2]     = Wmix[(2 * k2) * 64 + c];
        Wp[i * 2 + 1] = Wmix[(2 * k2 + 1) * 64 + c];
    }
    if (tid < 64)  bm_s[tid] = bmix[tid];
    if (tid < 128) bc_s[tid] = bconv[tid];
    __syncthreads();

    for (int idx = tid; idx < 64 * 128; idx += 256) {
        int nd = idx >> 7, c = idx & 127;
        int n = n0 + nd;
        float u = 0.f;
        if (n < N_NODES) u = g_acc[(size_t)n * 128 + c] + bc_s[c];
        u_s[nd * 130 + c] = u;
    }
    __syncthreads();

    int colg = tid & 15;
    int nodeg = tid >> 4;
    uint64_t acc2[4][4];
    #pragma unroll
    for (int i = 0; i < 4; i++)
        #pragma unroll
        for (int j = 0; j < 4; j++) acc2[i][j] = 0ull;

    #pragma unroll 4
    for (int k2 = 0; k2 < 64; k2++) {
        uint64_t w[4];
        #pragma unroll
        for (int j = 0; j < 4; j++)
            w[j] = *(const uint64_t*)&Wp[(k2 * 64 + colg + 16 * j) * 2];
        #pragma unroll
        for (int i = 0; i < 4; i++) {
            uint64_t uv = *(const uint64_t*)&u_s[(nodeg * 4 + i) * 130 + k2 * 2];
            #pragma unroll
            for (int j = 0; j < 4; j++) FMA2(acc2[i][j], uv, w[j]);
        }
    }

    #pragma unroll
    for (int i = 0; i < 4; i++) {
        int n = n0 + nodeg * 4 + i;
        if (n < N_NODES) {
            #pragma unroll
            for (int j = 0; j < 4; j++) {
                int col = colg + 16 * j;
                float h = hsum2(acc2[i][j]) + bm_s[col];
                g_h[(size_t)n * 64 + col] = fmaxf(h, 0.f);
            }
        }
    }
}

__device__ __forceinline__ float sigf(float x) { return 1.f / (1.f + expf(-x)); }

#define MMA16816(c0, c1, c2, c3, a0, a1, a2, a3, b0, b1) \
    asm volatile("mma.sync.aligned.m16n8k16.row.col.f32.f16.f16.f32 " \
                 "{%0,%1,%2,%3}, {%4,%5,%6,%7}, {%8,%9}, {%0,%1,%2,%3};" \
                 : "+f"(c0), "+f"(c1), "+f"(c2), "+f"(c3) \
                 : "r"(a0), "r"(a1), "r"(a2), "r"(a3), "r"(b0), "r"(b1))

// ---------------- GRU via fp16 mma.sync + output projection (persistent) ----------------
// smem layout (floats):
//   [0, 25088)          stage: gi [64][196] at 0; gh at 12544. ALIASED with fp16 W
//                       tiles (Wih16 [192][72] halves at 0, Whh16 next) used only
//                       during B-fragment extraction before the tile loop.
//   [25088, 27392)      h16  [64][72] halves (2304 floats)
//   [27392, 29696)      hp16 [64][72] halves
//   [29696, 34048)      hn   [64][68] floats
//   [34048, 34628)      bih 192 | bhh 192 | wo 192 | bo 4
__global__ __launch_bounds__(256, 1)
void k_gru_mma(const float* __restrict__ hprev,
               const float* __restrict__ Wih, const float* __restrict__ Whh,
               const float* __restrict__ bih, const float* __restrict__ bhh,
               const float* __restrict__ Wout, const float* __restrict__ bout,
               float* __restrict__ out_h, float* __restrict__ out_p) {
    extern __shared__ float smf[];
    float*  stage = smf;                          // [2][64][196]
    __half* Wih16 = (__half*)smf;                 // [192][72]
    __half* Whh16 = Wih16 + 192 * 72;             // [192][72]
    __half* h16   = (__half*)(smf + 25088);       // [64][72]
    __half* hp16  = h16 + 64 * 72;                // [64][72]
    float*  hnS   = smf + 29696;                  // [64][68]
    float*  bihS  = smf + 34048;
    float*  bhhS  = bihS + 192;
    float*  woS   = bhhS + 192;
    float*  boS   = woS + 192;

    int tid = threadIdx.x;
    int lane = tid & 31;
    int wrp = tid >> 5;
    int g = lane >> 2;            // 0..7
    int t = lane & 3;             // 0..3
    int cbase = wrp * 24;         // warp covers cols [cbase, cbase+24)

    // biases / Wout first (not aliased)
    if (tid < 192) {
        bihS[tid] = bih[tid];
        bhhS[tid] = bhh[tid];
        int j = tid / 3, k = tid % 3;
        woS[tid] = Wout[j * 64 + k];
    }
    if (tid < 3) boS[tid] = bout[tid];

    // load W fp16 into (aliased) smem
    for (int i = tid; i < 192 * 64; i += 256) {
        int r = i >> 6, k = i & 63;
        Wih16[r * 72 + k] = __float2half(Wih[i]);
        Whh16[r * 72 + k] = __float2half(Whh[i]);
    }
    __syncthreads();

    // extract B fragments into registers: [nt][ks][2]
    uint32_t Bi[3][4][2], Bh[3][4][2];
    #pragma unroll
    for (int nt = 0; nt < 3; nt++) {
        int n = cbase + nt * 8 + g;
        #pragma unroll
        for (int ks = 0; ks < 4; ks++) {
            Bi[nt][ks][0] = *(const uint32_t*)&Wih16[n * 72 + ks * 16 + 2 * t];
            Bi[nt][ks][1] = *(const uint32_t*)&Wih16[n * 72 + ks * 16 + 2 * t + 8];
            Bh[nt][ks][0] = *(const uint32_t*)&Whh16[n * 72 + ks * 16 + 2 * t];
            Bh[nt][ks][1] = *(const uint32_t*)&Whh16[n * 72 + ks * 16 + 2 * t + 8];
        }
    }
    __syncthreads();   // W area now dead; stage may reuse it

    for (int tile = blockIdx.x; tile < TILES; tile += gridDim.x) {
        int n0 = tile * 64;
        // load h (mix output) and hprev as fp16 tiles
        for (int i = tid; i < 64 * 64; i += 256) {
            int nd = i >> 6, k = i & 63;
            int n = n0 + nd;
            float hv = 0.f, pv = 0.f;
            if (n < N_NODES) {
                hv = g_h[(size_t)n * 64 + k];
                pv = hprev[(size_t)n * 64 + k];
            }
            h16[nd * 72 + k]  = __float2half(hv);
            hp16[nd * 72 + k] = __float2half(pv);
        }
        __syncthreads();

        float acc[2][4][3][4];
        #pragma unroll
        for (int mt = 0; mt < 2; mt++)
            #pragma unroll
            for (int m = 0; m < 4; m++)
                #pragma unroll
                for (int nt = 0; nt < 3; nt++)
                    #pragma unroll
                    for (int c = 0; c < 4; c++) acc[mt][m][nt][c] = 0.f;

        #pragma unroll
        for (int mt = 0; mt < 2; mt++) {
            const __half* A = mt ? hp16 : h16;
            #pragma unroll
            for (int ks = 0; ks < 4; ks++) {
                #pragma unroll
                for (int m = 0; m < 4; m++) {
                    int row = m * 16 + g;
                    int ko = ks * 16 + 2 * t;
                    uint32_t a0 = *(const uint32_t*)&A[row * 72 + ko];
                    uint32_t a1 = *(const uint32_t*)&A[(row + 8) * 72 + ko];
                    uint32_t a2 = *(const uint32_t*)&A[row * 72 + ko + 8];
                    uint32_t a3 = *(const uint32_t*)&A[(row + 8) * 72 + ko + 8];
                    #pragma unroll
                    for (int nt = 0; nt < 3; nt++) {
                        if (mt == 0) {
                            MMA16816(acc[0][m][nt][0], acc[0][m][nt][1],
                                     acc[0][m][nt][2], acc[0][m][nt][3],
                                     a0, a1, a2, a3, Bi[nt][ks][0], Bi[nt][ks][1]);
                        } else {
                            MMA16816(acc[1][m][nt][0], acc[1][m][nt][1],
                                     acc[1][m][nt][2], acc[1][m][nt][3],
                                     a0, a1, a2, a3, Bh[nt][ks][0], Bh[nt][ks][1]);
                        }
                    }
                }
            }
        }

        // stage gi/gh to smem
        #pragma unroll
        for (int mt = 0; mt < 2; mt++) {
            float* st = stage + mt * 12544;
            #pragma unroll
            for (int m = 0; m < 4; m++) {
                int row = m * 16 + g;
                #pragma unroll
                for (int nt = 0; nt < 3; nt++) {
                    int col = cbase + nt * 8 + 2 * t;
                    *(float2*)&st[row * 196 + col] =
                        make_float2(acc[mt][m][nt][0], acc[mt][m][nt][1]);
                    *(float2*)&st[(row + 8) * 196 + col] =
                        make_float2(acc[mt][m][nt][2], acc[mt][m][nt][3]);
                }
            }
        }
        __syncthreads();

        // gates: 16 (node,col) pairs per thread
        for (int i = tid; i < 64 * 64; i += 256) {
            int nd = i >> 6, j = i & 63;
            int n = n0 + nd;
            float ir = stage[nd * 196 + j]        + bihS[j];
            float iz = stage[nd * 196 + j + 64]   + bihS[64 + j];
            float in_ = stage[nd * 196 + j + 128] + bihS[128 + j];
            float hr = stage[12544 + nd * 196 + j]        + bhhS[j];
            float hz = stage[12544 + nd * 196 + j + 64]   + bhhS[64 + j];
            float hn = stage[12544 + nd * 196 + j + 128]  + bhhS[128 + j];
            float hp = (n < N_NODES) ? hprev[(size_t)n * 64 + j] : 0.f;
            float r = sigf(ir + hr);
            float z = sigf(iz + hz);
            float nn = tanhf(in_ + r * hn);
            float hx = (1.f - z) * nn + z * hp;
            if (n < N_NODES) out_h[(size_t)n * 64 + j] = hx;
            hnS[nd * 68 + j] = hx;
        }
        __syncthreads();

        // pred_xyz
        if (tid < 192) {
            int nd = tid / 3, k = tid % 3;
            int n = n0 + nd;
            if (n < N_NODES) {
                float a = boS[k];
                #pragma unroll
                for (int j = 0; j < 64; j++) a += hnS[nd * 68 + j] * woS[j * 3 + k];
                out_p[(size_t)n * 3 + k] = a;
            }
        }
        __syncthreads();
    }
}

extern "C" void kernel_launch(void* const* d_in, const int* in_sizes, int n_in,
                              void* d_out, int out_size) {
    const float* x       = (const float*)d_in[0];
    const float* h_prev  = (const float*)d_in[1];
    const int* en        = (const int*)d_in[2];
    const int* eh        = (const int*)d_in[3];
    const int* ea        = (const int*)d_in[4];
    const float* W_conv  = (const float*)d_in[5];
    const float* b_conv  = (const float*)d_in[6];
    const float* W_mix   = (const float*)d_in[7];
    const float* b_mix   = (const float*)d_in[8];
    const float* W_ih    = (const float*)d_in[9];
    const float* W_hh    = (const float*)d_in[10];
    const float* b_ih    = (const float*)d_in[11];
    const float* b_hh    = (const float*)d_in[12];
    const float* W_out   = (const float*)d_in[13];
    const float* b_out   = (const float*)d_in[14];
    float* out = (float*)d_out;
    float* out_h = out;
    float* out_p = out + (size_t)N_NODES * 64;

    static const int mix_smem = (8320 + 8192 + 64 + 128) * 4;
    static const int gru_smem = 34628 * 4;   // 138512 B
    cudaFuncSetAttribute(k_mix, cudaFuncAttributeMaxDynamicSharedMemorySize, mix_smem);
    cudaFuncSetAttribute(k_gru_mma, cudaFuncAttributeMaxDynamicSharedMemorySize, gru_smem);

    // sort phase
    k_zero_hist<<<(SB + 255) / 256, 256>>>();
    k_hist<<<(NE + 255) / 256, 256>>>(en, eh, ea);
    k_scan_local<<<NBB, 256>>>(0);
    k_scan_local<<<NBD, 256>>>(1);
    k_scan_tops<<<1, 512>>>(0);
    k_scan_tops<<<1, 512>>>(1);
    k_scan_add<<<(SB + 255) / 256, 256>>>(0);
    k_scan_add<<<(SD + 255) / 256, 256>>>(1);
    k_place<<<(NE + 255) / 256, 256>>>(en, eh, ea);

    // dense projection
    k_xw<<<N_NODES / 8, 128>>>(x, W_conv);

    // gather phases
    k_gather1<<<(SB * 8 + 255) / 256, 256>>>();
    k_gather2<<<(SD * 8 + 255) / 256, 256>>>();

    k_mix<<<(N_NODES + 63) / 64, 256, mix_smem>>>(W_mix, b_mix, b_conv);
    k_gru_mma<<<152, 256, gru_smem>>>(h_prev, W_ih, W_hh, b_ih, b_hh,
                                      W_out, b_out, out_h, out_p);
}